// round 4
// baseline (speedup 1.0000x reference)
#include <cuda_runtime.h>
#include <math.h>

#define Bn 256
#define Tn 250
#define Zn 128
#define Hn 256
#define Dn 512
#define Kn 20
#define Pn 123
#define TB (Tn*Bn)

typedef unsigned long long ull;

// ---------------- scratch ---------------------------------------------------
__device__ float g_hfT[2][Hn*Bn];   // [unit][batch]
__device__ float g_hbT[2][Hn*Bn];
__device__ float g_z  [Bn*Zn];
__device__ float g_zgT[4*Dn*Bn];    // [gatecol][batch] (includes dec_b + z@Wx_z)
__device__ float g_hdT[2][Dn*Bn];
__device__ float g_cdT[Dn*Bn];
__device__ float g_hsT[(size_t)Dn*TB];
__device__ int   g_bar[32];

__device__ __forceinline__ float sigf(float x) { return 1.0f / (1.0f + expf(-x)); }
__device__ __forceinline__ void ffma2(ull& d, ull a, ull b) {
    asm("fma.rn.f32x2 %0, %1, %2, %0;" : "+l"(d) : "l"(a), "l"(b));
}
__device__ __forceinline__ ull dup2(float w) {
    ull r; unsigned int u = __float_as_uint(w);
    asm("mov.b64 %0, {%1, %1};" : "=l"(r) : "r"(u));
    return r;
}
__device__ __forceinline__ float2 unpk(ull v) {
    float2 f; asm("mov.b64 {%0, %1}, %2;" : "=f"(f.x), "=f"(f.y) : "l"(v));
    return f;
}

__global__ void init_bar() { if (threadIdx.x < 32) g_bar[threadIdx.x] = 0; }

__device__ __forceinline__ void grp_barrier(int* ctr, int target) {
    __syncthreads();
    if (threadIdx.x == 0) {
        __threadfence();
        atomicAdd(ctr, 1);
        while (*(volatile int*)ctr < target) { }
    }
    __syncthreads();
}

// =================== persistent encoder =====================================
// 128 CTAs: dir(2) x btile(4, 64 batch) x utile(16, 16 units -> 64 gate cols)
// 128 threads: tx = unit (16), ty = row-group of 8.
#define EKR 262
#define ENC_SMEM ((EKR*64 + EKR*64) * 4)

__global__ __launch_bounds__(128) void enc_persist(
    const float* __restrict__ data,
    const float* __restrict__ Wx_f, const float* __restrict__ Wh_f, const float* __restrict__ b_f,
    const float* __restrict__ Wx_b, const float* __restrict__ Wh_b, const float* __restrict__ b_b)
{
    extern __shared__ float smem[];
    float* Wsm = smem;              // [262][64], col = unit*4 + gate
    float* Asm = smem + EKR * 64;   // [262][64]

    const int tid = threadIdx.x;
    const int bx  = blockIdx.x;
    const int dir = bx >> 6;
    const int bt  = (bx >> 4) & 3;
    const int ut  = bx & 15;
    const int b0  = bt * 64, u0 = ut * 16;

    const float* __restrict__ Wh = dir ? Wh_b : Wh_f;
    const float* __restrict__ Wx = dir ? Wx_b : Wx_f;
    const float* __restrict__ bb = dir ? b_b  : b_f;
    float* hbuf0 = dir ? g_hbT[0] : g_hfT[0];
    float* hbuf1 = dir ? g_hbT[1] : g_hfT[1];
    int* ctr = &g_bar[dir * 4 + bt];

    // one-time weight stage (Wh rows 0..255, Wx rows 256..260, bias row 261)
    for (int i = tid; i < EKR * 64; i += 128) {
        int k = i >> 6, c = i & 63;
        int u = c >> 2, g = c & 3;
        float v;
        if (k < 256)      v = Wh[k * (4 * Hn) + g * Hn + u0 + u];
        else if (k < 261) v = Wx[(k - 256) * (4 * Hn) + g * Hn + u0 + u];
        else              v = bb[g * Hn + u0 + u];
        Wsm[i] = v;
    }

    const int tx = tid & 15;       // unit
    const int ty = tid >> 4;       // row group of 8
    const int u  = u0 + tx;
    const int lb = (tid & 15) * 4; // batch float4 offset
    const int kr = tid >> 4;       // 0..7

    // zero initial h slice (units u0..u0+15 for this batch tile)
    for (int i = tid; i < 16 * 16; i += 128) {
        int uu = i >> 4, c4 = (i & 15) * 4;
        __stcg((float4*)&hbuf0[(u0 + uu) * Bn + b0 + c4], make_float4(0, 0, 0, 0));
    }
    float creg[8] = {0, 0, 0, 0, 0, 0, 0, 0};
    grp_barrier(ctr, 16);
    int s = 1;

    for (int t = 0; t < Tn; t++) {
        const float* hin = (t & 1) ? hbuf1 : hbuf0;
        float* hout      = (t & 1) ? hbuf0 : hbuf1;
        const int xtime  = dir ? (Tn - t) : (t + 1);

        // stage h (256 k rows x 64 batch)
        #pragma unroll 1
        for (int c = 0; c < 4; c++) {
            float4 tmp[8];
            #pragma unroll
            for (int i = 0; i < 8; i++) {
                int k = c * 64 + i * 8 + kr;
                tmp[i] = __ldcg((const float4*)&hin[k * Bn + b0 + lb]);
            }
            #pragma unroll
            for (int i = 0; i < 8; i++) {
                int k = c * 64 + i * 8 + kr;
                *(float4*)&Asm[k * 64 + lb] = tmp[i];
            }
        }
        if (tid < 64) {
            #pragma unroll
            for (int j = 0; j < 5; j++)
                Asm[(256 + j) * 64 + tid] =
                    __ldg(&data[(size_t)(b0 + tid) * ((Tn + 1) * 5) + xtime * 5 + j]);
            Asm[261 * 64 + tid] = 1.0f;
        }
        __syncthreads();

        ull acc[4][4] = {};   // [rowpair][gate]
        #pragma unroll 4
        for (int k = 0; k < EKR; k++) {
            const float* ar = &Asm[k * 64 + ty * 8];
            ull a0 = *(const ull*)&ar[0];
            ull a1 = *(const ull*)&ar[2];
            ull a2 = *(const ull*)&ar[4];
            ull a3 = *(const ull*)&ar[6];
            float4 w = *(const float4*)&Wsm[k * 64 + tx * 4];
            ull w0 = dup2(w.x), w1 = dup2(w.y), w2 = dup2(w.z), w3 = dup2(w.w);
            ffma2(acc[0][0], a0, w0); ffma2(acc[0][1], a0, w1);
            ffma2(acc[0][2], a0, w2); ffma2(acc[0][3], a0, w3);
            ffma2(acc[1][0], a1, w0); ffma2(acc[1][1], a1, w1);
            ffma2(acc[1][2], a1, w2); ffma2(acc[1][3], a1, w3);
            ffma2(acc[2][0], a2, w0); ffma2(acc[2][1], a2, w1);
            ffma2(acc[2][2], a2, w2); ffma2(acc[2][3], a2, w3);
            ffma2(acc[3][0], a3, w0); ffma2(acc[3][1], a3, w1);
            ffma2(acc[3][2], a3, w2); ffma2(acc[3][3], a3, w3);
        }

        float pg[8][4];
        #pragma unroll
        for (int pr = 0; pr < 4; pr++)
            #pragma unroll
            for (int g = 0; g < 4; g++) {
                float2 v = unpk(acc[pr][g]);
                pg[pr * 2][g] = v.x; pg[pr * 2 + 1][g] = v.y;
            }
        float hreg[8];
        #pragma unroll
        for (int r = 0; r < 8; r++) {
            float cn = sigf(pg[r][1]) * creg[r] + sigf(pg[r][0]) * tanhf(pg[r][2]);
            hreg[r] = sigf(pg[r][3]) * tanhf(cn);
            creg[r] = cn;
        }
        __stcg((float4*)&hout[u * Bn + b0 + ty * 8],
               make_float4(hreg[0], hreg[1], hreg[2], hreg[3]));
        __stcg((float4*)&hout[u * Bn + b0 + ty * 8 + 4],
               make_float4(hreg[4], hreg[5], hreg[6], hreg[7]));

        if (t < Tn - 1) { grp_barrier(ctr, 16 * (s + 1)); s++; }
    }
}

// =================== persistent decoder =====================================
// 128 CTAs: btile(4, 64 batch) x utile(32, 16 units -> 64 gate cols)
// 128 threads: tx = unit (16), ty = row-group of 8. Two K passes of 256.
#define DKR 517
#define DEC_SMEM ((DKR*64 + 261*64) * 4)

__global__ __launch_bounds__(128) void dec_persist(
    const float* __restrict__ data,
    const float* __restrict__ dec_Wx, const float* __restrict__ Wh)
{
    extern __shared__ float smem[];
    float* Wsm = smem;              // [517][64]
    float* Asm = smem + DKR * 64;   // [261][64]

    const int tid = threadIdx.x;
    const int bt  = blockIdx.x >> 5;
    const int ut  = blockIdx.x & 31;
    const int b0  = bt * 64, u0 = ut * 16;
    int* ctr = &g_bar[16 + bt];

    for (int i = tid; i < DKR * 64; i += 128) {
        int k = i >> 6, c = i & 63;
        int uu = c >> 2, g = c & 3;
        float v;
        if (k < 512) v = Wh[k * (4 * Dn) + g * Dn + u0 + uu];
        else         v = dec_Wx[(k - 512) * (4 * Dn) + g * Dn + u0 + uu];
        Wsm[i] = v;
    }

    const int tx = tid & 15;
    const int ty = tid >> 4;
    const int u  = u0 + tx;
    const int lb = (tid & 15) * 4;
    const int kr = tid >> 4;

    float zrf[4][8];
    #pragma unroll
    for (int g = 0; g < 4; g++) {
        float4 z0 = *(const float4*)&g_zgT[((size_t)g * Dn + u) * Bn + b0 + ty * 8];
        float4 z1 = *(const float4*)&g_zgT[((size_t)g * Dn + u) * Bn + b0 + ty * 8 + 4];
        zrf[g][0] = z0.x; zrf[g][1] = z0.y; zrf[g][2] = z0.z; zrf[g][3] = z0.w;
        zrf[g][4] = z1.x; zrf[g][5] = z1.y; zrf[g][6] = z1.z; zrf[g][7] = z1.w;
    }
    float creg[8];
    {
        float4 c0 = *(const float4*)&g_cdT[u * Bn + b0 + ty * 8];
        float4 c1 = *(const float4*)&g_cdT[u * Bn + b0 + ty * 8 + 4];
        creg[0] = c0.x; creg[1] = c0.y; creg[2] = c0.z; creg[3] = c0.w;
        creg[4] = c1.x; creg[5] = c1.y; creg[6] = c1.z; creg[7] = c1.w;
    }
    __syncthreads();
    int s = 0;

    for (int t = 0; t < Tn; t++) {
        const float* hin = (t & 1) ? g_hdT[1] : g_hdT[0];
        float* hout      = (t & 1) ? g_hdT[0] : g_hdT[1];
        ull acc[4][4] = {};

        #pragma unroll 1
        for (int p = 0; p < 2; p++) {
            #pragma unroll 1
            for (int c = 0; c < 4; c++) {
                float4 tmp[8];
                #pragma unroll
                for (int i = 0; i < 8; i++) {
                    int k = p * 256 + c * 64 + i * 8 + kr;
                    tmp[i] = __ldcg((const float4*)&hin[(size_t)k * Bn + b0 + lb]);
                }
                #pragma unroll
                for (int i = 0; i < 8; i++) {
                    int k = c * 64 + i * 8 + kr;
                    *(float4*)&Asm[k * 64 + lb] = tmp[i];
                }
            }
            if (p == 1 && tid < 64) {
                #pragma unroll
                for (int j = 0; j < 5; j++)
                    Asm[(256 + j) * 64 + tid] =
                        __ldg(&data[(size_t)(b0 + tid) * ((Tn + 1) * 5) + t * 5 + j]);
            }
            __syncthreads();

            const int KL = p ? 261 : 256;
            const float* Wp = Wsm + p * 256 * 64;
            #pragma unroll 4
            for (int k = 0; k < KL; k++) {
                const float* ar = &Asm[k * 64 + ty * 8];
                ull a0 = *(const ull*)&ar[0];
                ull a1 = *(const ull*)&ar[2];
                ull a2 = *(const ull*)&ar[4];
                ull a3 = *(const ull*)&ar[6];
                float4 w = *(const float4*)&Wp[k * 64 + tx * 4];
                ull w0 = dup2(w.x), w1 = dup2(w.y), w2 = dup2(w.z), w3 = dup2(w.w);
                ffma2(acc[0][0], a0, w0); ffma2(acc[0][1], a0, w1);
                ffma2(acc[0][2], a0, w2); ffma2(acc[0][3], a0, w3);
                ffma2(acc[1][0], a1, w0); ffma2(acc[1][1], a1, w1);
                ffma2(acc[1][2], a1, w2); ffma2(acc[1][3], a1, w3);
                ffma2(acc[2][0], a2, w0); ffma2(acc[2][1], a2, w1);
                ffma2(acc[2][2], a2, w2); ffma2(acc[2][3], a2, w3);
                ffma2(acc[3][0], a3, w0); ffma2(acc[3][1], a3, w1);
                ffma2(acc[3][2], a3, w2); ffma2(acc[3][3], a3, w3);
            }
            if (p == 0) __syncthreads();
        }

        float pg[8][4];
        #pragma unroll
        for (int pr = 0; pr < 4; pr++)
            #pragma unroll
            for (int g = 0; g < 4; g++) {
                float2 v = unpk(acc[pr][g]);
                pg[pr * 2][g]     = v.x + zrf[g][pr * 2];
                pg[pr * 2 + 1][g] = v.y + zrf[g][pr * 2 + 1];
            }
        float hreg[8];
        #pragma unroll
        for (int r = 0; r < 8; r++) {
            float cn = sigf(pg[r][1]) * creg[r] + sigf(pg[r][0]) * tanhf(pg[r][2]);
            hreg[r] = sigf(pg[r][3]) * tanhf(cn);
            creg[r] = cn;
        }
        float4 h0 = make_float4(hreg[0], hreg[1], hreg[2], hreg[3]);
        float4 h1 = make_float4(hreg[4], hreg[5], hreg[6], hreg[7]);
        __stcg((float4*)&hout[u * Bn + b0 + ty * 8], h0);
        __stcg((float4*)&hout[u * Bn + b0 + ty * 8 + 4], h1);
        *(float4*)&g_hsT[(size_t)u * TB + (size_t)t * Bn + b0 + ty * 8] = h0;
        *(float4*)&g_hsT[(size_t)u * TB + (size_t)t * Bn + b0 + ty * 8 + 4] = h1;

        if (t < Tn - 1) { grp_barrier(ctr, 32 * (s + 1)); s++; }
    }
}

// =================== latent stages ==========================================
__global__ void latent1(const float* __restrict__ W, const float* __restrict__ bias,
                        const float* __restrict__ eps,
                        float* __restrict__ zm, float* __restrict__ zl)
{
    int b = blockIdx.x, j = threadIdx.x;
    float sm = bias[j], sl = bias[j + Zn];
    for (int k = 0; k < Hn; k++) {
        float a = g_hfT[0][k * Bn + b];
        sm = fmaf(a, W[k * (2 * Zn) + j], sm);
        sl = fmaf(a, W[k * (2 * Zn) + Zn + j], sl);
    }
    for (int k = 0; k < Hn; k++) {
        float a = g_hbT[0][k * Bn + b];
        sm = fmaf(a, W[(Hn + k) * (2 * Zn) + j], sm);
        sl = fmaf(a, W[(Hn + k) * (2 * Zn) + Zn + j], sl);
    }
    zm[b * Zn + j] = sm;
    zl[b * Zn + j] = sl;
    g_z[b * Zn + j] = sm + expf(0.5f * sl) * eps[b * Zn + j];
}

// grid (8 btiles, 24 coltiles), 256 threads; CTA = 32 batch x 128 cols, K=128
__global__ __launch_bounds__(256) void latent2(
    const float* __restrict__ init_W, const float* __restrict__ init_b,
    const float* __restrict__ dec_Wx, const float* __restrict__ dec_b)
{
    __shared__ float zs[32][Zn];
    const int tid = threadIdx.x;
    const int tx = tid & 31, ty = tid >> 5;
    const int b0 = blockIdx.x * 32;
    const int col0 = blockIdx.y * 128;
    const bool isInit = (col0 < 2 * Dn);

    for (int i = tid; i < 32 * Zn; i += 256) {
        int r = i >> 7, k = i & 127;
        zs[r][k] = g_z[(b0 + r) * Zn + k];
    }
    __syncthreads();

    const int col = col0 + tx * 4;
    const float* Wcol;
    if (isInit) Wcol = init_W + col;
    else        Wcol = dec_Wx + 5 * (4 * Dn) + (col - 2 * Dn);
    const int wstride = isInit ? (2 * Dn) : (4 * Dn);

    float acc[4][4] = {};
    #pragma unroll 4
    for (int k = 0; k < Zn; k++) {
        float4 w = *(const float4*)&Wcol[k * wstride];
        float a0 = zs[ty * 4 + 0][k], a1 = zs[ty * 4 + 1][k];
        float a2 = zs[ty * 4 + 2][k], a3 = zs[ty * 4 + 3][k];
        acc[0][0] = fmaf(a0, w.x, acc[0][0]); acc[0][1] = fmaf(a0, w.y, acc[0][1]);
        acc[0][2] = fmaf(a0, w.z, acc[0][2]); acc[0][3] = fmaf(a0, w.w, acc[0][3]);
        acc[1][0] = fmaf(a1, w.x, acc[1][0]); acc[1][1] = fmaf(a1, w.y, acc[1][1]);
        acc[1][2] = fmaf(a1, w.z, acc[1][2]); acc[1][3] = fmaf(a1, w.w, acc[1][3]);
        acc[2][0] = fmaf(a2, w.x, acc[2][0]); acc[2][1] = fmaf(a2, w.y, acc[2][1]);
        acc[2][2] = fmaf(a2, w.z, acc[2][2]); acc[2][3] = fmaf(a2, w.w, acc[2][3]);
        acc[3][0] = fmaf(a3, w.x, acc[3][0]); acc[3][1] = fmaf(a3, w.y, acc[3][1]);
        acc[3][2] = fmaf(a3, w.z, acc[3][2]); acc[3][3] = fmaf(a3, w.w, acc[3][3]);
    }

    #pragma unroll
    for (int r = 0; r < 4; r++) {
        int b = b0 + ty * 4 + r;
        #pragma unroll
        for (int c = 0; c < 4; c++) {
            int cc = col + c;
            if (isInit) {
                float v = tanhf(acc[r][c] + init_b[cc]);
                if (cc < Dn) g_hdT[0][cc * Bn + b] = v;
                else         g_cdT[(cc - Dn) * Bn + b] = v;
            } else {
                int c2 = cc - 2 * Dn;
                g_zgT[(size_t)c2 * Bn + b] = acc[r][c] + dec_b[c2];
            }
        }
    }
}

// =================== output head ============================================
__global__ __launch_bounds__(256) void mix_kernel(
    const float* __restrict__ Wm, const float* __restrict__ bm, float* __restrict__ out)
{
    __shared__ __align__(16) float As[32][32];
    __shared__ __align__(16) float Ws[32][128];
    __shared__ float ys[32 * 129];
    const int tid = threadIdx.x;
    const int tx = tid & 31, ty = tid >> 5;
    const int row0 = blockIdx.x * 32;
    ull acc[2][4] = {};

    for (int k0 = 0; k0 < Dn; k0 += 32) {
        __syncthreads();
        {
            int k = tid >> 3, c = (tid & 7) * 4;
            float4 v = *(const float4*)&g_hsT[(size_t)(k0 + k) * TB + row0 + c];
            *(float4*)&As[k][c] = v;
        }
        for (int i = tid; i < 32 * 128; i += 256) {
            int k = i >> 7, c = i & 127;
            Ws[k][c] = (c < Pn) ? Wm[(k0 + k) * Pn + c] : 0.f;
        }
        __syncthreads();
        #pragma unroll 4
        for (int k = 0; k < 32; k++) {
            ull a01 = *(const ull*)&As[k][ty * 4];
            ull a23 = *(const ull*)&As[k][ty * 4 + 2];
            float4 w = *(const float4*)&Ws[k][tx * 4];
            ull w0 = dup2(w.x), w1 = dup2(w.y), w2 = dup2(w.z), w3 = dup2(w.w);
            ffma2(acc[0][0], a01, w0); ffma2(acc[0][1], a01, w1);
            ffma2(acc[0][2], a01, w2); ffma2(acc[0][3], a01, w3);
            ffma2(acc[1][0], a23, w0); ffma2(acc[1][1], a23, w1);
            ffma2(acc[1][2], a23, w2); ffma2(acc[1][3], a23, w3);
        }
    }

    #pragma unroll
    for (int pr = 0; pr < 2; pr++)
        #pragma unroll
        for (int c = 0; c < 4; c++) {
            float2 v = unpk(acc[pr][c]);
            int cc = tx * 4 + c;
            float bias = (cc < Pn) ? bm[cc] : 0.f;
            ys[(ty * 4 + pr * 2 + 0) * 129 + cc] = v.x + bias;
            ys[(ty * 4 + pr * 2 + 1) * 129 + cc] = v.y + bias;
        }
    __syncthreads();

    if (tid < 32) {
        int row = row0 + tid;
        int tt = row >> 8;
        int bb2 = row & 255;
        float* o = out + ((size_t)bb2 * Tn + tt) * Pn;
        const float* y = &ys[tid * 129];
        float m = y[0];
        #pragma unroll
        for (int j = 1; j < Kn; j++) m = fmaxf(m, y[j]);
        float e[Kn]; float sum = 0.f;
        #pragma unroll
        for (int j = 0; j < Kn; j++) { e[j] = expf(y[j] - m); sum += e[j]; }
        float inv = 1.f / sum;
        #pragma unroll
        for (int j = 0; j < Kn; j++) o[j] = e[j] * inv;
        #pragma unroll
        for (int j = Kn; j < 3 * Kn; j++) o[j] = y[j];
        #pragma unroll
        for (int j = 3 * Kn; j < 5 * Kn; j++) o[j] = expf(y[j]);
        #pragma unroll
        for (int j = 5 * Kn; j < 6 * Kn; j++) o[j] = tanhf(y[j]);
        o[120] = y[120]; o[121] = y[121]; o[122] = y[122];
    }
}

// =================== launcher ================================================
extern "C" void kernel_launch(void* const* d_in, const int* in_sizes, int n_in,
                              void* d_out, int out_size)
{
    (void)in_sizes; (void)n_in; (void)out_size;
    const float* data      = (const float*)d_in[0];
    const float* eps       = (const float*)d_in[1];
    const float* enc_Wx_f  = (const float*)d_in[2];
    const float* enc_Wh_f  = (const float*)d_in[3];
    const float* enc_b_f   = (const float*)d_in[4];
    const float* enc_Wx_b  = (const float*)d_in[5];
    const float* enc_Wh_b  = (const float*)d_in[6];
    const float* enc_b_b   = (const float*)d_in[7];
    const float* enc_out_W = (const float*)d_in[8];
    const float* enc_out_b = (const float*)d_in[9];
    const float* init_W    = (const float*)d_in[10];
    const float* init_b    = (const float*)d_in[11];
    const float* dec_Wx    = (const float*)d_in[12];
    const float* dec_Wh    = (const float*)d_in[13];
    const float* dec_b     = (const float*)d_in[14];
    const float* mix_W     = (const float*)d_in[15];
    const float* mix_b     = (const float*)d_in[16];
    float* out = (float*)d_out;

    cudaFuncSetAttribute(enc_persist, cudaFuncAttributeMaxDynamicSharedMemorySize, ENC_SMEM);
    cudaFuncSetAttribute(dec_persist, cudaFuncAttributeMaxDynamicSharedMemorySize, DEC_SMEM);

    const size_t params_sz = (size_t)Bn * Tn * Pn;

    init_bar<<<1, 32>>>();
    enc_persist<<<128, 128, ENC_SMEM>>>(data, enc_Wx_f, enc_Wh_f, enc_b_f,
                                        enc_Wx_b, enc_Wh_b, enc_b_b);
    latent1<<<Bn, 128>>>(enc_out_W, enc_out_b, eps,
                         out + params_sz, out + params_sz + (size_t)Bn * Zn);
    latent2<<<dim3(8, 24), 256>>>(init_W, init_b, dec_Wx, dec_b);
    dec_persist<<<128, 128, DEC_SMEM>>>(data, dec_Wx, dec_Wh);
    mix_kernel<<<TB / 32, 256>>>(mix_W, mix_b, out);
}